// round 6
// baseline (speedup 1.0000x reference)
#include <cuda_runtime.h>
#include <cuda_bf16.h>
#include <math.h>

// Problem constants
#define BB   8
#define CC   256
#define HW   40000          // 200*200
#define HW4  10000          // HW / 4
#define KK   8000           // int(0.2 * HW)

// Scratch (allocation-free rule: __device__ globals)
__device__ unsigned g_score_u[BB * HW];   // float bits of sum(x^2) (nonneg -> uint order == float order)
__device__ float    g_sim[BB * HW];       // per-pixel cosine similarity
__device__ double   g_bsum[BB];           // per-batch sum of selected sims

// ---------------------------------------------------------------------------
// Kernel 1: fused per-pixel channel statistics -> score + cosine sim.
// Same per-thread code as the 108us version (unroll 4), but block=64 /
// grid=1250 for fine wave granularity: 313 CTAs left a 17-CTA straggler
// wave (1.42x quantization waste); 1250 CTAs -> ~8.5/SM -> 1.07x.
// ---------------------------------------------------------------------------
__global__ void __launch_bounds__(64) k_stats(const float* __restrict__ bev,
                                              const float* __restrict__ pri) {
    int idx = blockIdx.x * 64 + threadIdx.x;   // 1250*64 = 80000 exact
    int b  = idx / HW4;
    int p4 = idx - b * HW4;

    const float4* pb = reinterpret_cast<const float4*>(bev + (size_t)b * CC * HW) + p4;
    const float4* pp = reinterpret_cast<const float4*>(pri + (size_t)b * CC * HW) + p4;

    float4 sb  = {0.f, 0.f, 0.f, 0.f};
    float4 sp  = {0.f, 0.f, 0.f, 0.f};
    float4 sbb = {0.f, 0.f, 0.f, 0.f};
    float4 spp = {0.f, 0.f, 0.f, 0.f};
    float4 sbp = {0.f, 0.f, 0.f, 0.f};

#pragma unroll 4
    for (int c = 0; c < CC; c++) {
        float4 x = __ldg(pb + c * HW4);
        float4 y = __ldg(pp + c * HW4);
#define ACC(f)                                \
        sb.f  += x.f;                         \
        sp.f  += y.f;                         \
        sbb.f  = fmaf(x.f, x.f, sbb.f);       \
        spp.f  = fmaf(y.f, y.f, spp.f);       \
        sbp.f  = fmaf(x.f, y.f, sbp.f);
        ACC(x) ACC(y) ACC(z) ACC(w)
#undef ACC
    }

    const float invC  = 1.0f / (float)CC;
    const float invC1 = 1.0f / (float)(CC - 1);
    int obase = b * HW + p4 * 4;

#define EMIT(f, j) {                                                        \
        float Sb = sb.f, Sp = sp.f, Sb2 = sbb.f, Sp2 = spp.f, Sxp = sbp.f;  \
        float SSb = fmaxf(Sb2 - Sb * Sb * invC, 0.0f);                      \
        float SSp = fmaxf(Sp2 - Sp * Sp * invC, 0.0f);                      \
        float Cov = Sxp - Sb * Sp * invC;                                   \
        float sgb = sqrtf(SSb * invC1) + 1e-6f;                             \
        float sgp = sqrtf(SSp * invC1) + 1e-6f;                             \
        float na  = sqrtf(SSb) / sgb;                                       \
        float nb  = sqrtf(SSp) / sgp;                                       \
        float sim = (Cov / (sgb * sgp)) /                                   \
                    (fmaxf(na, 1e-8f) * fmaxf(nb, 1e-8f));                  \
        g_score_u[obase + j] = __float_as_uint(Sb2);                        \
        g_sim[obase + j]     = sim;                                         \
    }
    EMIT(x, 0) EMIT(y, 1) EMIT(z, 2) EMIT(w, 3)
#undef EMIT
}

// ---------------------------------------------------------------------------
// Kernel 2 (fused): radix select + top-k sim sum. One block per batch.
// Scores smem-resident (one batched uint4 sweep). Histogram updates are
// WARP-AGGREGATED: scores concentrate into 1-2 bins, and a 32-lane
// same-address smem atomic costs 32cyc/warp serialized; match_any + leader
// popc atomic makes it one single-lane atomic per distinct bin per warp.
// ---------------------------------------------------------------------------
__global__ void __launch_bounds__(1024) k_select_sum() {
    extern __shared__ unsigned sc[];     // 40000 score words (160 KB)
    int b = blockIdx.x;
    const uint4*  s4   = reinterpret_cast<const uint4*>(g_score_u + b * HW);
    const float4* sim4 = reinterpret_cast<const float4*>(g_sim + b * HW);
    uint4* sc4 = reinterpret_cast<uint4*>(sc);

    __shared__ unsigned hist8[8][256];   // privatized histogram copies
    __shared__ unsigned hist[256];       // merged
    __shared__ unsigned sh_prefix;
    __shared__ int sh_k;
    __shared__ int sh_tie;
    __shared__ float red[32];

    const int tid  = threadIdx.x;
    const int lane = tid & 31;
    const int wid  = tid >> 5;
    const int grp  = wid >> 2;           // 0..7

    if (tid == 0) { sh_prefix = 0u; sh_k = KK; sh_tie = 0; }

    // ---- load all scores into smem (coalesced uint4, independent loads) ----
    for (int i = tid; i < HW4; i += 1024)
        sc4[i] = s4[i];
    __syncthreads();

    // ---- radix select over smem-resident scores ----
    for (int pass = 0; pass < 4; pass++) {
        int shift = 24 - 8 * pass;
        unsigned mask = (pass == 0) ? 0u : (0xFFFFFFFFu << (shift + 8));
        hist8[tid >> 8][tid & 255] = 0u;
        hist8[(tid >> 8) + 4][tid & 255] = 0u;
        __syncthreads();
        unsigned prefix = sh_prefix;
        for (int i = tid; i < HW; i += 1024) {
            unsigned u = sc[i];
            bool act = (u & mask) == prefix;
            unsigned bin = (u >> shift) & 255u;
            unsigned key = act ? bin : 0xFFFFFFFFu;
            unsigned m = __match_any_sync(0xFFFFFFFFu, key);
            if (act) {
                int leader = __ffs(m) - 1;
                if (lane == leader)
                    atomicAdd(&hist8[grp][bin], (unsigned)__popc(m));
            }
        }
        __syncthreads();
        if (tid < 256) {
            unsigned t = 0;
#pragma unroll
            for (int g = 0; g < 8; g++) t += hist8[g][tid];
            hist[tid] = t;
        }
        __syncthreads();
        if (tid == 0) {
            int kk = sh_k;
            int bin = 255;
            for (; bin > 0; bin--) {
                int c = (int)hist[bin];
                if (kk <= c) break;
                kk -= c;
            }
            sh_prefix = prefix | ((unsigned)bin << shift);
            sh_k = kk;
        }
        __syncthreads();
    }

    unsigned T = sh_prefix;
    int needed = sh_k;

    // ---- sum sims over top-k: vectorized global sim loads + smem scores ----
    float local = 0.0f;
    for (int i = tid; i < HW4; i += 1024) {
        float4 sm = sim4[i];          // independent 128-bit loads, high MLP
        uint4  u  = sc4[i];
#define SEL(f, j) {                                                 \
            unsigned uu = u.f;                                      \
            if (uu > T) {                                           \
                local += sm.j;                                      \
            } else if (uu == T) {                                   \
                int pos = atomicAdd(&sh_tie, 1);                    \
                if (pos < needed) local += sm.j;                    \
            }                                                       \
        }
        SEL(x, x) SEL(y, y) SEL(z, z) SEL(w, w)
#undef SEL
    }

    // block reduction
    for (int off = 16; off > 0; off >>= 1)
        local += __shfl_down_sync(0xFFFFFFFFu, local, off);
    if (lane == 0) red[wid] = local;
    __syncthreads();
    if (wid == 0) {
        float v = red[lane];
        for (int off = 16; off > 0; off >>= 1)
            v += __shfl_down_sync(0xFFFFFFFFu, v, off);
        if (lane == 0) g_bsum[b] = (double)v;
    }
}

// ---------------------------------------------------------------------------
// Kernel 3: finalize -> scalar loss
// ---------------------------------------------------------------------------
__global__ void k_finalize(const float* __restrict__ dx,
                           const float* __restrict__ dy,
                           const float* __restrict__ dt,
                           float* __restrict__ out) {
    if (threadIdx.x == 0 && blockIdx.x == 0) {
        double total = 0.0;
        for (int i = 0; i < BB; i++) total += g_bsum[i];
        double mean_sim = total / (double)(BB * KK);
        float align = (float)(1.0 - mean_sim);
        float r1 = 0.f, r2 = 0.f;
        for (int i = 0; i < BB; i++) {
            r1 += dx[i] * dx[i] + dy[i] * dy[i];
            r2 += dt[i] * dt[i];
        }
        float reg = r1 * (1.0f / BB) + r2 * (1.0f / BB);
        out[0] = align + 0.1f * reg;
    }
}

extern "C" void kernel_launch(void* const* d_in, const int* in_sizes, int n_in,
                              void* d_out, int out_size) {
    const float* bev = (const float*)d_in[0];
    const float* pri = (const float*)d_in[1];
    const float* dx  = (const float*)d_in[2];
    const float* dy  = (const float*)d_in[3];
    const float* dt  = (const float*)d_in[4];
    float* out = (float*)d_out;

    k_stats<<<1250, 64>>>(bev, pri);      // 80000 float4-groups, exact

    const int SMEM_SEL = HW * (int)sizeof(unsigned);   // 160000 B
    cudaFuncSetAttribute(k_select_sum,
                         cudaFuncAttributeMaxDynamicSharedMemorySize, SMEM_SEL);
    k_select_sum<<<BB, 1024, SMEM_SEL>>>();

    k_finalize<<<1, 32>>>(dx, dy, dt, out);
}

// round 7
// speedup vs baseline: 1.0377x; 1.0377x over previous
#include <cuda_runtime.h>
#include <cuda_bf16.h>
#include <math.h>

// Problem constants
#define BB   8
#define CC   256
#define HW   40000          // 200*200
#define HW4  10000          // HW / 4
#define KK   8000           // int(0.2 * HW)

#define HPAD 257             // histogram row stride: 257 % 32 != 0 -> copies of
                             // the same bin land in 8 DISTINCT banks

// Scratch (allocation-free rule: __device__ globals)
__device__ unsigned g_score_u[BB * HW];   // float bits of sum(x^2) (nonneg -> uint order == float order)
__device__ float    g_sim[BB * HW];       // per-pixel cosine similarity
__device__ double   g_bsum[BB];           // per-batch sum of selected sims

// ---------------------------------------------------------------------------
// Kernel 1: fused per-pixel channel statistics -> score + cosine sim.
// grid=1250 x block=64 (R6 config: 104us @ DRAM 80%; fine wave granularity).
// ---------------------------------------------------------------------------
__global__ void __launch_bounds__(64) k_stats(const float* __restrict__ bev,
                                              const float* __restrict__ pri) {
    int idx = blockIdx.x * 64 + threadIdx.x;   // 1250*64 = 80000 exact
    int b  = idx / HW4;
    int p4 = idx - b * HW4;

    const float4* pb = reinterpret_cast<const float4*>(bev + (size_t)b * CC * HW) + p4;
    const float4* pp = reinterpret_cast<const float4*>(pri + (size_t)b * CC * HW) + p4;

    float4 sb  = {0.f, 0.f, 0.f, 0.f};
    float4 sp  = {0.f, 0.f, 0.f, 0.f};
    float4 sbb = {0.f, 0.f, 0.f, 0.f};
    float4 spp = {0.f, 0.f, 0.f, 0.f};
    float4 sbp = {0.f, 0.f, 0.f, 0.f};

#pragma unroll 4
    for (int c = 0; c < CC; c++) {
        float4 x = __ldg(pb + c * HW4);
        float4 y = __ldg(pp + c * HW4);
#define ACC(f)                                \
        sb.f  += x.f;                         \
        sp.f  += y.f;                         \
        sbb.f  = fmaf(x.f, x.f, sbb.f);       \
        spp.f  = fmaf(y.f, y.f, spp.f);       \
        sbp.f  = fmaf(x.f, y.f, sbp.f);
        ACC(x) ACC(y) ACC(z) ACC(w)
#undef ACC
    }

    const float invC  = 1.0f / (float)CC;
    const float invC1 = 1.0f / (float)(CC - 1);
    int obase = b * HW + p4 * 4;

#define EMIT(f, j) {                                                        \
        float Sb = sb.f, Sp = sp.f, Sb2 = sbb.f, Sp2 = spp.f, Sxp = sbp.f;  \
        float SSb = fmaxf(Sb2 - Sb * Sb * invC, 0.0f);                      \
        float SSp = fmaxf(Sp2 - Sp * Sp * invC, 0.0f);                      \
        float Cov = Sxp - Sb * Sp * invC;                                   \
        float sgb = sqrtf(SSb * invC1) + 1e-6f;                             \
        float sgp = sqrtf(SSp * invC1) + 1e-6f;                             \
        float na  = sqrtf(SSb) / sgb;                                       \
        float nb  = sqrtf(SSp) / sgp;                                       \
        float sim = (Cov / (sgb * sgp)) /                                   \
                    (fmaxf(na, 1e-8f) * fmaxf(nb, 1e-8f));                  \
        g_score_u[obase + j] = __float_as_uint(Sb2);                        \
        g_sim[obase + j]     = sim;                                         \
    }
    EMIT(x, 0) EMIT(y, 1) EMIT(z, 2) EMIT(w, 3)
#undef EMIT
}

// ---------------------------------------------------------------------------
// Kernel 2 (fused): radix select + top-k sim sum. One block per batch.
// Scores smem-resident. Direct privatized atomics (match_any regressed 2x).
// Histogram rows padded to 257 words: the old 256-stride put all 8 copies
// of a bin in the SAME bank (256 % 32 == 0), serializing the concentrated
// pass-0 bin at 32cyc/warp across all warps (~22us). 257 gives 8-way bank
// parallelism.
// ---------------------------------------------------------------------------
__global__ void __launch_bounds__(1024) k_select_sum() {
    extern __shared__ unsigned sc[];     // 40000 score words (160 KB)
    int b = blockIdx.x;
    const uint4*  s4   = reinterpret_cast<const uint4*>(g_score_u + b * HW);
    const float4* sim4 = reinterpret_cast<const float4*>(g_sim + b * HW);
    uint4* sc4 = reinterpret_cast<uint4*>(sc);

    __shared__ unsigned hist8[8 * HPAD]; // privatized, bank-spread copies
    __shared__ unsigned hist[256];       // merged
    __shared__ unsigned sh_prefix;
    __shared__ int sh_k;
    __shared__ int sh_tie;
    __shared__ float red[32];

    const int tid  = threadIdx.x;
    const int lane = tid & 31;
    const int wid  = tid >> 5;
    const int hbase = (wid >> 2) * HPAD; // group 0..7 -> its padded copy

    if (tid == 0) { sh_prefix = 0u; sh_k = KK; sh_tie = 0; }

    // ---- load all scores into smem (coalesced uint4, independent loads) ----
    for (int i = tid; i < HW4; i += 1024)
        sc4[i] = s4[i];
    __syncthreads();

    // ---- radix select over smem-resident scores ----
    for (int pass = 0; pass < 4; pass++) {
        int shift = 24 - 8 * pass;
        unsigned mask = (pass == 0) ? 0u : (0xFFFFFFFFu << (shift + 8));
        for (int i = tid; i < 8 * HPAD; i += 1024) hist8[i] = 0u;
        __syncthreads();
        unsigned prefix = sh_prefix;
        for (int i = tid; i < HW; i += 1024) {
            unsigned u = sc[i];
            if ((u & mask) == prefix)
                atomicAdd(&hist8[hbase + ((u >> shift) & 255u)], 1u);
        }
        __syncthreads();
        if (tid < 256) {
            unsigned t = 0;
#pragma unroll
            for (int g = 0; g < 8; g++) t += hist8[g * HPAD + tid];
            hist[tid] = t;
        }
        __syncthreads();
        if (tid == 0) {
            int kk = sh_k;
            int bin = 255;
            for (; bin > 0; bin--) {
                int c = (int)hist[bin];
                if (kk <= c) break;
                kk -= c;
            }
            sh_prefix = prefix | ((unsigned)bin << shift);
            sh_k = kk;
        }
        __syncthreads();
    }

    unsigned T = sh_prefix;
    int needed = sh_k;

    // ---- sum sims over top-k: vectorized global sim loads + smem scores ----
    float local = 0.0f;
    for (int i = tid; i < HW4; i += 1024) {
        float4 sm = sim4[i];          // independent 128-bit loads, high MLP
        uint4  u  = sc4[i];
#define SEL(f, j) {                                                 \
            unsigned uu = u.f;                                      \
            if (uu > T) {                                           \
                local += sm.j;                                      \
            } else if (uu == T) {                                   \
                int pos = atomicAdd(&sh_tie, 1);                    \
                if (pos < needed) local += sm.j;                    \
            }                                                       \
        }
        SEL(x, x) SEL(y, y) SEL(z, z) SEL(w, w)
#undef SEL
    }

    // block reduction
    for (int off = 16; off > 0; off >>= 1)
        local += __shfl_down_sync(0xFFFFFFFFu, local, off);
    if (lane == 0) red[wid] = local;
    __syncthreads();
    if (wid == 0) {
        float v = red[lane];
        for (int off = 16; off > 0; off >>= 1)
            v += __shfl_down_sync(0xFFFFFFFFu, v, off);
        if (lane == 0) g_bsum[b] = (double)v;
    }
}

// ---------------------------------------------------------------------------
// Kernel 3: finalize -> scalar loss
// ---------------------------------------------------------------------------
__global__ void k_finalize(const float* __restrict__ dx,
                           const float* __restrict__ dy,
                           const float* __restrict__ dt,
                           float* __restrict__ out) {
    if (threadIdx.x == 0 && blockIdx.x == 0) {
        double total = 0.0;
        for (int i = 0; i < BB; i++) total += g_bsum[i];
        double mean_sim = total / (double)(BB * KK);
        float align = (float)(1.0 - mean_sim);
        float r1 = 0.f, r2 = 0.f;
        for (int i = 0; i < BB; i++) {
            r1 += dx[i] * dx[i] + dy[i] * dy[i];
            r2 += dt[i] * dt[i];
        }
        float reg = r1 * (1.0f / BB) + r2 * (1.0f / BB);
        out[0] = align + 0.1f * reg;
    }
}

extern "C" void kernel_launch(void* const* d_in, const int* in_sizes, int n_in,
                              void* d_out, int out_size) {
    const float* bev = (const float*)d_in[0];
    const float* pri = (const float*)d_in[1];
    const float* dx  = (const float*)d_in[2];
    const float* dy  = (const float*)d_in[3];
    const float* dt  = (const float*)d_in[4];
    float* out = (float*)d_out;

    k_stats<<<1250, 64>>>(bev, pri);      // 80000 float4-groups, exact

    const int SMEM_SEL = HW * (int)sizeof(unsigned);   // 160000 B
    cudaFuncSetAttribute(k_select_sum,
                         cudaFuncAttributeMaxDynamicSharedMemorySize, SMEM_SEL);
    k_select_sum<<<BB, 1024, SMEM_SEL>>>();

    k_finalize<<<1, 32>>>(dx, dy, dt, out);
}

// round 8
// speedup vs baseline: 1.1835x; 1.1404x over previous
#include <cuda_runtime.h>
#include <cuda_bf16.h>
#include <math.h>

// Problem constants
#define BB   8
#define CC   256
#define HW   40000          // 200*200
#define HW4  10000          // HW / 4
#define KK   8000           // int(0.2 * HW)
#define NB16 65536           // 16-bit key histogram bins

// Scratch (allocation-free rule: __device__ globals)
__device__ unsigned g_score_u[BB * HW];    // float bits of sum(x^2) (>=0: uint order == float order)
__device__ float    g_sim[BB * HW];        // per-pixel cosine similarity
__device__ unsigned g_hist16[BB * NB16];   // per-batch histogram of (score_bits >> 16)
__device__ double   g_bsum[BB];            // per-batch sum of selected sims

// ---------------------------------------------------------------------------
// Kernel 0: zero the 16-bit-key histograms (graph replay safety).
// 512 x 256 threads x uint4 = exactly BB*NB16 words.
// ---------------------------------------------------------------------------
__global__ void k_zero() {
    uint4* h4 = reinterpret_cast<uint4*>(g_hist16);
    h4[blockIdx.x * 256 + threadIdx.x] = make_uint4(0u, 0u, 0u, 0u);
}

// ---------------------------------------------------------------------------
// Kernel 1: fused per-pixel channel statistics -> score + cosine sim,
// PLUS a global 16-bit-key score histogram (spread REDG atomics over ~256
// occupied bins/batch -- hidden under the DRAM-bound stream; this removes
// the two expensive top-byte radix passes from the select kernel).
// grid=1250 x block=64 (R6 config: 104us @ DRAM 80%).
// ---------------------------------------------------------------------------
__global__ void __launch_bounds__(64) k_stats(const float* __restrict__ bev,
                                              const float* __restrict__ pri) {
    int idx = blockIdx.x * 64 + threadIdx.x;   // 1250*64 = 80000 exact
    int b  = idx / HW4;
    int p4 = idx - b * HW4;

    const float4* pb = reinterpret_cast<const float4*>(bev + (size_t)b * CC * HW) + p4;
    const float4* pp = reinterpret_cast<const float4*>(pri + (size_t)b * CC * HW) + p4;

    float4 sb  = {0.f, 0.f, 0.f, 0.f};
    float4 sp  = {0.f, 0.f, 0.f, 0.f};
    float4 sbb = {0.f, 0.f, 0.f, 0.f};
    float4 spp = {0.f, 0.f, 0.f, 0.f};
    float4 sbp = {0.f, 0.f, 0.f, 0.f};

#pragma unroll 4
    for (int c = 0; c < CC; c++) {
        float4 x = __ldg(pb + c * HW4);
        float4 y = __ldg(pp + c * HW4);
#define ACC(f)                                \
        sb.f  += x.f;                         \
        sp.f  += y.f;                         \
        sbb.f  = fmaf(x.f, x.f, sbb.f);       \
        spp.f  = fmaf(y.f, y.f, spp.f);       \
        sbp.f  = fmaf(x.f, y.f, sbp.f);
        ACC(x) ACC(y) ACC(z) ACC(w)
#undef ACC
    }

    const float invC  = 1.0f / (float)CC;
    const float invC1 = 1.0f / (float)(CC - 1);
    int obase = b * HW + p4 * 4;
    unsigned* hist = g_hist16 + b * NB16;

#define EMIT(f, j) {                                                        \
        float Sb = sb.f, Sp = sp.f, Sb2 = sbb.f, Sp2 = spp.f, Sxp = sbp.f;  \
        float SSb = fmaxf(Sb2 - Sb * Sb * invC, 0.0f);                      \
        float SSp = fmaxf(Sp2 - Sp * Sp * invC, 0.0f);                      \
        float Cov = Sxp - Sb * Sp * invC;                                   \
        float sgb = sqrtf(SSb * invC1) + 1e-6f;                             \
        float sgp = sqrtf(SSp * invC1) + 1e-6f;                             \
        float na  = sqrtf(SSb) / sgb;                                       \
        float nb  = sqrtf(SSp) / sgp;                                       \
        float sim = (Cov / (sgb * sgp)) /                                   \
                    (fmaxf(na, 1e-8f) * fmaxf(nb, 1e-8f));                  \
        unsigned su = __float_as_uint(Sb2);                                 \
        g_score_u[obase + j] = su;                                          \
        g_sim[obase + j]     = sim;                                         \
        atomicAdd(&hist[su >> 16], 1u);                                     \
    }
    EMIT(x, 0) EMIT(y, 1) EMIT(z, 2) EMIT(w, 3)
#undef EMIT
}

// ---------------------------------------------------------------------------
// Kernel 2: per-batch exact top-k threshold + sim sum. One block per batch.
//  A) suffix-scan the 65536-bin global histogram -> 16-bit prefix B16 + k1
//  B) two 8-bit radix passes over smem-cached scores RESTRICTED to the
//     ~(HW/256) elements matching B16 (atomics negligible) -> exact T, needed
//  C) one vectorized sweep summing sims of score > T (+ ties up to needed)
// ---------------------------------------------------------------------------
__global__ void __launch_bounds__(1024) k_select_sum() {
    extern __shared__ unsigned sc[];     // 40000 score words (160 KB)
    int b = blockIdx.x;
    const uint4*  s4   = reinterpret_cast<const uint4*>(g_score_u + b * HW);
    const float4* sim4 = reinterpret_cast<const float4*>(g_sim + b * HW);
    const unsigned* hist = g_hist16 + b * NB16;
    uint4* sc4 = reinterpret_cast<uint4*>(sc);

    __shared__ unsigned chunk[1024];     // per-thread 64-bin sums -> suffix scan
    __shared__ unsigned h256[256];
    __shared__ unsigned sh_B16, sh_T;
    __shared__ int sh_k1, sh_k2, sh_needed, sh_tie;
    __shared__ float red[32];

    const int tid  = threadIdx.x;
    const int lane = tid & 31;
    const int wid  = tid >> 5;

    if (tid == 0) sh_tie = 0;

    // ---- load all scores into smem (coalesced uint4, independent loads) ----
    for (int i = tid; i < HW4; i += 1024)
        sc4[i] = s4[i];

    // ---- Stage A: chunk sums of the 16-bit histogram (64 bins/thread) ----
    {
        const uint4* h4 = reinterpret_cast<const uint4*>(hist) + tid * 16;
        unsigned t = 0;
#pragma unroll
        for (int i = 0; i < 16; i++) {
            uint4 v = h4[i];
            t += v.x + v.y + v.z + v.w;
        }
        chunk[tid] = t;
    }
    __syncthreads();
    // inclusive suffix scan over 1024 chunks (Hillis-Steele)
    for (int off = 1; off < 1024; off <<= 1) {
        unsigned v = chunk[tid] + ((tid + off < 1024) ? chunk[tid + off] : 0u);
        __syncthreads();
        chunk[tid] = v;
        __syncthreads();
    }
    // locate crossing chunk, then serial scan of its 64 bins from the top
    {
        unsigned incl = chunk[tid];
        unsigned excl = (tid < 1023) ? chunk[tid + 1] : 0u;
        if (excl < KK && incl >= KK) {
            int kk = KK - (int)excl;
            for (int bin = tid * 64 + 63; bin >= tid * 64; bin--) {
                int c = (int)hist[bin];
                if (kk <= c) { sh_B16 = (unsigned)bin; sh_k1 = kk; break; }
                kk -= c;
            }
        }
    }
    __syncthreads();
    unsigned B16 = sh_B16;

    // ---- Stage B pass 1: bits 15..8 among elements with key16 == B16 ----
    if (tid < 256) h256[tid] = 0u;
    __syncthreads();
    for (int i = tid; i < HW; i += 1024) {
        unsigned u = sc[i];
        if ((u >> 16) == B16) atomicAdd(&h256[(u >> 8) & 255u], 1u);
    }
    __syncthreads();
    if (tid == 0) {
        int kk = sh_k1;
        int bin = 255;
        for (; bin > 0; bin--) {
            int c = (int)h256[bin];
            if (kk <= c) break;
            kk -= c;
        }
        sh_T = (B16 << 16) | ((unsigned)bin << 8);
        sh_k2 = kk;
    }
    __syncthreads();
    unsigned P24 = sh_T >> 8;     // 24-bit prefix

    // ---- Stage B pass 2: bits 7..0 among elements with prefix24 == P24 ----
    if (tid < 256) h256[tid] = 0u;
    __syncthreads();
    for (int i = tid; i < HW; i += 1024) {
        unsigned u = sc[i];
        if ((u >> 8) == P24) atomicAdd(&h256[u & 255u], 1u);
    }
    __syncthreads();
    if (tid == 0) {
        int kk = sh_k2;
        int bin = 255;
        for (; bin > 0; bin--) {
            int c = (int)h256[bin];
            if (kk <= c) break;
            kk -= c;
        }
        sh_T = (P24 << 8) | (unsigned)bin;
        sh_needed = kk;
    }
    __syncthreads();
    unsigned T = sh_T;
    int needed = sh_needed;

    // ---- Stage C: sum sims over top-k ----
    float local = 0.0f;
    for (int i = tid; i < HW4; i += 1024) {
        float4 sm = sim4[i];          // independent 128-bit loads, high MLP
        uint4  u  = sc4[i];
#define SEL(f, j) {                                                 \
            unsigned uu = u.f;                                      \
            if (uu > T) {                                           \
                local += sm.j;                                      \
            } else if (uu == T) {                                   \
                int pos = atomicAdd(&sh_tie, 1);                    \
                if (pos < needed) local += sm.j;                    \
            }                                                       \
        }
        SEL(x, x) SEL(y, y) SEL(z, z) SEL(w, w)
#undef SEL
    }

    // block reduction
    for (int off = 16; off > 0; off >>= 1)
        local += __shfl_down_sync(0xFFFFFFFFu, local, off);
    if (lane == 0) red[wid] = local;
    __syncthreads();
    if (wid == 0) {
        float v = red[lane];
        for (int off = 16; off > 0; off >>= 1)
            v += __shfl_down_sync(0xFFFFFFFFu, v, off);
        if (lane == 0) g_bsum[b] = (double)v;
    }
}

// ---------------------------------------------------------------------------
// Kernel 3: finalize -> scalar loss
// ---------------------------------------------------------------------------
__global__ void k_finalize(const float* __restrict__ dx,
                           const float* __restrict__ dy,
                           const float* __restrict__ dt,
                           float* __restrict__ out) {
    if (threadIdx.x == 0 && blockIdx.x == 0) {
        double total = 0.0;
        for (int i = 0; i < BB; i++) total += g_bsum[i];
        double mean_sim = total / (double)(BB * KK);
        float align = (float)(1.0 - mean_sim);
        float r1 = 0.f, r2 = 0.f;
        for (int i = 0; i < BB; i++) {
            r1 += dx[i] * dx[i] + dy[i] * dy[i];
            r2 += dt[i] * dt[i];
        }
        float reg = r1 * (1.0f / BB) + r2 * (1.0f / BB);
        out[0] = align + 0.1f * reg;
    }
}

extern "C" void kernel_launch(void* const* d_in, const int* in_sizes, int n_in,
                              void* d_out, int out_size) {
    const float* bev = (const float*)d_in[0];
    const float* pri = (const float*)d_in[1];
    const float* dx  = (const float*)d_in[2];
    const float* dy  = (const float*)d_in[3];
    const float* dt  = (const float*)d_in[4];
    float* out = (float*)d_out;

    k_zero<<<512, 256>>>();               // reset histograms (replay-safe)

    k_stats<<<1250, 64>>>(bev, pri);      // 80000 float4-groups, exact

    const int SMEM_SEL = HW * (int)sizeof(unsigned);   // 160000 B
    cudaFuncSetAttribute(k_select_sum,
                         cudaFuncAttributeMaxDynamicSharedMemorySize, SMEM_SEL);
    k_select_sum<<<BB, 1024, SMEM_SEL>>>();

    k_finalize<<<1, 32>>>(dx, dy, dt, out);
}